// round 1
// baseline (speedup 1.0000x reference)
#include <cuda_runtime.h>
#include <cuda_bf16.h>
#include <math.h>

#define H 192
#define MAXB 200000
#define EPSLN 1e-5f

// Scratch (device globals: allowed; no runtime allocation)
__device__ int   g_first[MAXB + 1];
__device__ float g_dist[MAXB];
__device__ float g_h[2 * MAXB * H];   // residual stream: rows [0,B)=h1, [B,2B)=h2

// ---------------------------------------------------------------------------
// Kernel 1: find first atom index of each molecule (batch is sorted)
// ---------------------------------------------------------------------------
__global__ __launch_bounds__(256)
void findfirst_kernel(const int* __restrict__ batch, int N, int B)
{
    int i = blockIdx.x * blockDim.x + threadIdx.x;
    if (i == 0) g_first[B] = N;           // sentinel
    if (i >= N) return;
    if (i == 0 || batch[i] != batch[i - 1])
        g_first[batch[i]] = i;
}

// ---------------------------------------------------------------------------
// Kernel 2: gather initial embeddings into g_h (rows m = h1, rows B+m = h2)
// ---------------------------------------------------------------------------
__global__ __launch_bounds__(256)
void gather_kernel(const int* __restrict__ z, const float* __restrict__ emb, int B)
{
    int idx = blockIdx.x * blockDim.x + threadIdx.x;
    int total = 2 * B * H;
    if (idx >= total) return;
    int r = idx / H;
    int c = idx - r * H;
    int m = (r < B) ? r : (r - B);
    int f  = g_first[m];
    int nf = g_first[m + 1];
    int atom = f;
    if (r >= B && (nf - f) > 1) atom = f + 1;
    g_h[idx] = emb[z[atom] * H + c];
}

// ---------------------------------------------------------------------------
// Kernel 3: per-molecule pair distance
// ---------------------------------------------------------------------------
__global__ __launch_bounds__(256)
void dist_kernel(const float* __restrict__ pos, int B)
{
    int m = blockIdx.x * blockDim.x + threadIdx.x;
    if (m >= B) return;
    int f  = g_first[m];
    int nf = g_first[m + 1];
    float d = 0.f;
    if (nf - f > 1) {
        int s = f + 1;
        float dx = pos[3 * f + 0] - pos[3 * s + 0];
        float dy = pos[3 * f + 1] - pos[3 * s + 1];
        float dz = pos[3 * f + 2] - pos[3 * s + 2];
        d = sqrtf(dx * dx + dy * dy + dz * dz + 1e-12f);
    }
    g_dist[m] = d;
}

// ---------------------------------------------------------------------------
// Kernel 4: fused residual-MLP layer.
// Block: 64 rows x 192 cols output tile; 256 threads; thread tile 8x6.
// h <- h + relu(LN(h @ W^T + b) * g + beta)
// Dynamic smem: Hs[64][192] (input rows, also residual) + Wt[32][193].
// ---------------------------------------------------------------------------
__global__ __launch_bounds__(256)
void layer_kernel(const float* __restrict__ W,
                  const float* __restrict__ bias,
                  const float* __restrict__ gamma,
                  const float* __restrict__ beta,
                  int nrows)
{
    extern __shared__ float sm[];
    float* Hs = sm;                 // [64][192], stride 192
    float* Wt = sm + 64 * H;        // [32][193]

    const int tid = threadIdx.x;
    const int tx = tid & 31;
    const int ty = tid >> 5;
    const int row0 = blockIdx.x * 64;

    // Load 64 input rows (full K) into smem
    for (int e = tid; e < 64 * H; e += 256) {
        int r = e / H, k = e - r * H;
        int row = row0 + r;
        Hs[e] = (row < nrows) ? g_h[row * H + k] : 0.f;
    }

    float acc[8][6];
#pragma unroll
    for (int rr = 0; rr < 8; rr++)
#pragma unroll
        for (int j = 0; j < 6; j++) acc[rr][j] = 0.f;

    for (int k0 = 0; k0 < H; k0 += 32) {
        __syncthreads();    // also covers initial Hs load on first iter
        // Stage W[o][k0..k0+31] transposed: Wt[kk][o]
        for (int e = tid; e < H * 32; e += 256) {
            int o = e >> 5, kk = e & 31;
            Wt[kk * 193 + o] = W[o * H + k0 + kk];
        }
        __syncthreads();
#pragma unroll
        for (int kk = 0; kk < 32; kk++) {
            float bv[6];
#pragma unroll
            for (int j = 0; j < 6; j++) bv[j] = Wt[kk * 193 + tx + 32 * j];
#pragma unroll
            for (int rr = 0; rr < 8; rr++) {
                float a = Hs[(ty * 8 + rr) * H + k0 + kk];
#pragma unroll
                for (int j = 0; j < 6; j++) acc[rr][j] = fmaf(a, bv[j], acc[rr][j]);
            }
        }
    }

    // Epilogue: bias + LayerNorm + ReLU + residual, all in-warp.
    float lb[6], lg[6], lbt[6];
#pragma unroll
    for (int j = 0; j < 6; j++) {
        int c = tx + 32 * j;
        lb[j] = bias[c]; lg[j] = gamma[c]; lbt[j] = beta[c];
    }
    const float inv = 1.f / (float)H;
#pragma unroll
    for (int rr = 0; rr < 8; rr++) {
        int row = row0 + ty * 8 + rr;
        if (row >= nrows) continue;           // uniform across warp
        float s = 0.f, s2 = 0.f;
#pragma unroll
        for (int j = 0; j < 6; j++) {
            float y = acc[rr][j] + lb[j];
            acc[rr][j] = y;
            s += y; s2 += y * y;
        }
#pragma unroll
        for (int o = 16; o > 0; o >>= 1) {
            s  += __shfl_xor_sync(0xffffffffu, s,  o);
            s2 += __shfl_xor_sync(0xffffffffu, s2, o);
        }
        float mu = s * inv;
        float var = s2 * inv - mu * mu;
        float rstd = rsqrtf(var + EPSLN);
#pragma unroll
        for (int j = 0; j < 6; j++) {
            float v = (acc[rr][j] - mu) * rstd * lg[j] + lbt[j];
            v = fmaxf(v, 0.f);
            int c = tx + 32 * j;
            g_h[row * H + c] = Hs[(ty * 8 + rr) * H + c] + v;
        }
    }
}

// ---------------------------------------------------------------------------
// Kernel 5: fused head.
// Block: 64 molecules x 192 hidden; K=576 (h1|h2|dist_feat built on the fly).
// out[m] = relu(combined @ W1^T + b1) . W2 + b2
// ---------------------------------------------------------------------------
__global__ __launch_bounds__(256)
void head_kernel(const float* __restrict__ W1,
                 const float* __restrict__ b1,
                 const float* __restrict__ W2,
                 const float* __restrict__ b2,
                 const float* __restrict__ distW,
                 const float* __restrict__ distB,
                 float* __restrict__ out, int B)
{
    __shared__ float As[64 * 33];
    __shared__ float Wt[32 * 193];

    const int tid = threadIdx.x;
    const int tx = tid & 31;
    const int ty = tid >> 5;
    const int row0 = blockIdx.x * 64;

    float acc[8][6];
#pragma unroll
    for (int rr = 0; rr < 8; rr++)
#pragma unroll
        for (int j = 0; j < 6; j++) acc[rr][j] = 0.f;

    for (int k0 = 0; k0 < 3 * H; k0 += 32) {
        __syncthreads();
        // Stage A tile: combined[row0..row0+63][k0..k0+31]
        for (int e = tid; e < 64 * 32; e += 256) {
            int r = e >> 5, kk = e & 31;
            int m = row0 + r;
            int k = k0 + kk;
            float v = 0.f;
            if (m < B) {
                if (k < H)            v = g_h[m * H + k];
                else if (k < 2 * H)   v = g_h[(B + m) * H + (k - H)];
                else                  v = g_dist[m] * distW[k - 2 * H] + distB[k - 2 * H];
            }
            As[r * 33 + kk] = v;
        }
        // Stage W1[o][k0..k0+31] transposed
        for (int e = tid; e < H * 32; e += 256) {
            int o = e >> 5, kk = e & 31;
            Wt[kk * 193 + o] = W1[o * 3 * H + k0 + kk];
        }
        __syncthreads();
#pragma unroll
        for (int kk = 0; kk < 32; kk++) {
            float bv[6];
#pragma unroll
            for (int j = 0; j < 6; j++) bv[j] = Wt[kk * 193 + tx + 32 * j];
#pragma unroll
            for (int rr = 0; rr < 8; rr++) {
                float a = As[(ty * 8 + rr) * 33 + kk];
#pragma unroll
                for (int j = 0; j < 6; j++) acc[rr][j] = fmaf(a, bv[j], acc[rr][j]);
            }
        }
    }

    float lb1[6], lw2[6];
#pragma unroll
    for (int j = 0; j < 6; j++) {
        int c = tx + 32 * j;
        lb1[j] = b1[c]; lw2[j] = W2[c];
    }
    float bias2 = b2[0];
#pragma unroll
    for (int rr = 0; rr < 8; rr++) {
        int m = row0 + ty * 8 + rr;
        if (m >= B) continue;                 // uniform across warp
        float s = 0.f;
#pragma unroll
        for (int j = 0; j < 6; j++) {
            float x = fmaxf(acc[rr][j] + lb1[j], 0.f);
            s = fmaf(x, lw2[j], s);
        }
#pragma unroll
        for (int o = 16; o > 0; o >>= 1)
            s += __shfl_xor_sync(0xffffffffu, s, o);
        if (tx == 0) out[m] = s + bias2;
    }
}

// ---------------------------------------------------------------------------
extern "C" void kernel_launch(void* const* d_in, const int* in_sizes, int n_in,
                              void* d_out, int out_size)
{
    const int*   z         = (const int*)  d_in[1];
    const float* pos       = (const float*)d_in[2];
    const int*   batch     = (const int*)  d_in[3];
    const float* emb       = (const float*)d_in[5];
    const float* layer_W   = (const float*)d_in[6];
    const float* layer_b   = (const float*)d_in[7];
    const float* layer_g   = (const float*)d_in[8];
    const float* layer_bt  = (const float*)d_in[9];
    const float* dist_W    = (const float*)d_in[10];
    const float* dist_b    = (const float*)d_in[11];
    const float* head_W1   = (const float*)d_in[12];
    const float* head_b1   = (const float*)d_in[13];
    const float* head_W2   = (const float*)d_in[14];
    const float* head_b2   = (const float*)d_in[15];
    float* out = (float*)d_out;

    const int B = out_size;                 // molecules
    const int N = in_sizes[1];              // atoms
    const int L = in_sizes[6] / (H * H);    // layers
    const int nrows = 2 * B;

    const int layer_smem = (64 * H + 32 * 193) * (int)sizeof(float);  // 73856 B
    cudaFuncSetAttribute(layer_kernel, cudaFuncAttributeMaxDynamicSharedMemorySize, layer_smem);

    findfirst_kernel<<<(N + 255) / 256, 256>>>(batch, N, B);
    {
        int total = 2 * B * H;
        gather_kernel<<<(total + 255) / 256, 256>>>(z, emb, B);
    }
    dist_kernel<<<(B + 255) / 256, 256>>>(pos, B);

    for (int l = 0; l < L; l++) {
        layer_kernel<<<(nrows + 63) / 64, 256, layer_smem>>>(
            layer_W + (size_t)l * H * H,
            layer_b + l * H, layer_g + l * H, layer_bt + l * H,
            nrows);
    }

    head_kernel<<<(B + 63) / 64, 256>>>(head_W1, head_b1, head_W2, head_b2,
                                        dist_W, dist_b, out, B);
}

// round 3
// speedup vs baseline: 1.0990x; 1.0990x over previous
#include <cuda_runtime.h>
#include <cuda_bf16.h>
#include <math.h>
#include <stdint.h>

#define H 192
#define H3 576
#define MAXB 200000
#define EPSLN 1e-5f

typedef unsigned long long u64t;

// ===== device scratch (no runtime allocation) =====
__device__ int   g_first[MAXB + 1];
__device__ float g_dist[MAXB];
__device__ __nv_bfloat16 g_hhi[2 * MAXB * H];
__device__ __nv_bfloat16 g_hlo[2 * MAXB * H];
__device__ __nv_bfloat16 g_dfhi[MAXB * H];
__device__ __nv_bfloat16 g_dflo[MAXB * H];
__device__ __nv_bfloat16 g_Whi[5 * H * H];
__device__ __nv_bfloat16 g_Wlo[5 * H * H];
__device__ __nv_bfloat16 g_W1hi[H * H3];
__device__ __nv_bfloat16 g_W1lo[H * H3];

// ===== helpers =====
__device__ __forceinline__ uint32_t smem_u32(const void* p) {
    uint32_t a;
    asm("{ .reg .u64 t; cvta.to.shared.u64 t, %1; cvt.u32.u64 %0, t; }" : "=r"(a) : "l"(p));
    return a;
}
__device__ __forceinline__ void ldsm4(uint32_t* r, uint32_t addr) {
    asm volatile("ldmatrix.sync.aligned.m8n8.x4.shared.b16 {%0,%1,%2,%3}, [%4];"
        : "=r"(r[0]), "=r"(r[1]), "=r"(r[2]), "=r"(r[3]) : "r"(addr));
}
__device__ __forceinline__ void mma_bf16(float* c, const uint32_t* a, const uint32_t* b) {
    asm volatile("mma.sync.aligned.m16n8k16.row.col.f32.bf16.bf16.f32 "
        "{%0,%1,%2,%3}, {%4,%5,%6,%7}, {%8,%9}, {%0,%1,%2,%3};"
        : "+f"(c[0]), "+f"(c[1]), "+f"(c[2]), "+f"(c[3])
        : "r"(a[0]), "r"(a[1]), "r"(a[2]), "r"(a[3]), "r"(b[0]), "r"(b[1]));
}
__device__ __forceinline__ void fsplit(float x, __nv_bfloat16& hi, __nv_bfloat16& lo) {
    hi = __float2bfloat16_rn(x);
    lo = __float2bfloat16_rn(x - __bfloat162float(hi));
}

// ===== prep kernels =====
__global__ __launch_bounds__(256)
void findfirst_kernel(const int* __restrict__ batch, int N, int B) {
    int i = blockIdx.x * blockDim.x + threadIdx.x;
    if (i == 0) g_first[B] = N;
    if (i >= N) return;
    if (i == 0 || batch[i] != batch[i - 1]) g_first[batch[i]] = i;
}

__global__ __launch_bounds__(256)
void gather_kernel(const int* __restrict__ z, const float* __restrict__ emb, int B) {
    int idx = blockIdx.x * blockDim.x + threadIdx.x;
    if (idx >= 2 * B * H) return;
    int r = idx / H, c = idx - r * H;
    int m = (r < B) ? r : (r - B);
    int f = g_first[m], nf = g_first[m + 1];
    int atom = (r >= B && (nf - f) > 1) ? f + 1 : f;
    __nv_bfloat16 hi, lo;
    fsplit(emb[z[atom] * H + c], hi, lo);
    g_hhi[idx] = hi; g_hlo[idx] = lo;
}

__global__ __launch_bounds__(256)
void dist_kernel(const float* __restrict__ pos, int B) {
    int m = blockIdx.x * blockDim.x + threadIdx.x;
    if (m >= B) return;
    int f = g_first[m], nf = g_first[m + 1];
    float d = 0.f;
    if (nf - f > 1) {
        int s = f + 1;
        float dx = pos[3*f+0]-pos[3*s+0], dy = pos[3*f+1]-pos[3*s+1], dz = pos[3*f+2]-pos[3*s+2];
        d = sqrtf(dx*dx + dy*dy + dz*dz + 1e-12f);
    }
    g_dist[m] = d;
}

__global__ __launch_bounds__(256)
void distfeat_kernel(const float* __restrict__ dW, const float* __restrict__ dB, int B) {
    int idx = blockIdx.x * blockDim.x + threadIdx.x;
    if (idx >= B * H) return;
    int m = idx / H, c = idx - m * H;
    float v = g_dist[m] * dW[c] + dB[c];
    __nv_bfloat16 hi, lo; fsplit(v, hi, lo);
    g_dfhi[idx] = hi; g_dflo[idx] = lo;
}

__global__ __launch_bounds__(256)
void convw_kernel(const float* __restrict__ lW, const float* __restrict__ hW1, int L) {
    int idx = blockIdx.x * blockDim.x + threadIdx.x;
    int nlw = L * H * H;
    int tot = nlw + H * H3;
    if (idx >= tot) return;
    __nv_bfloat16 hi, lo;
    if (idx < nlw) { fsplit(lW[idx], hi, lo); g_Whi[idx] = hi; g_Wlo[idx] = lo; }
    else { int j = idx - nlw; fsplit(hW1[j], hi, lo); g_W1hi[j] = hi; g_W1lo[j] = lo; }
}

// =====================================================================
// Layer kernel: h <- h + relu(LN(h @ W^T + b)*g + beta), via mma.sync bf16 split.
// Block 256 thr, tile M=64 x N=192, warps 2(M)x4(N), warp tile 32x48.
// smem: Ahi[64x200*2B]=25600 | Alo 25600 | W[2 arrays 192x72*2B]=55296 (reused as Y 64x200xf32)
//       | prm 576 floats
// =====================================================================
#define AST 400     // A row stride bytes (200 bf16)
#define WST 144     // W row stride bytes (72 bf16)
#define L_ALO 25600
#define L_W   51200
#define L_WLO 27648 // lo offset within W region
#define L_PRM 106496
#define L_SMEM (106496 + 2304)

__global__ __launch_bounds__(256, 2)
void layer_mm_kernel(int l, const float* __restrict__ bias,
                     const float* __restrict__ gamma, const float* __restrict__ beta,
                     int nrows) {
    extern __shared__ __align__(128) char sm[];
    char* Ahi = sm;
    char* Alo = sm + L_ALO;
    char* Wb  = sm + L_W;
    float* prm = (float*)(sm + L_PRM);

    const int tid = threadIdx.x;
    const int wid = tid >> 5, lane = tid & 31;
    const int row0 = blockIdx.x * 64;

    for (int e = tid; e < 3 * H; e += 256)
        prm[e] = (e < H) ? bias[e] : (e < 2*H) ? gamma[e - H] : beta[e - 2*H];

    // stage A tile (full K=192), hi+lo
    for (int u = tid; u < 64 * 48; u += 256) {
        int r = u / 48, t = u - r * 48;
        u64t vh = 0, vl = 0;
        if (row0 + r < nrows) {
            size_t g = (size_t)(row0 + r) * H + t * 4;
            vh = *(const u64t*)(g_hhi + g);
            vl = *(const u64t*)(g_hlo + g);
        }
        *(u64t*)(Ahi + r * AST + t * 8) = vh;
        *(u64t*)(Alo + r * AST + t * 8) = vl;
    }

    const int wm = (wid & 1) * 32;          // warp M offset
    const int wn = (wid >> 1) * 48;         // warp N offset
    float acc[2][6][4];
#pragma unroll
    for (int mi = 0; mi < 2; mi++)
#pragma unroll
        for (int ni = 0; ni < 6; ni++)
#pragma unroll
            for (int j = 0; j < 4; j++) acc[mi][ni][j] = 0.f;

    const __nv_bfloat16* wh = g_Whi + l * H * H;
    const __nv_bfloat16* wl = g_Wlo + l * H * H;
    const uint32_t sbA  = smem_u32(Ahi);
    const uint32_t sbAl = smem_u32(Alo);
    const uint32_t sbW  = smem_u32(Wb);

    // ldmatrix lane addressing
    const int lr = lane & 15;                 // A: row within 16
    const int lk = (lane >> 4) << 3;          // A: +8 cols for upper half
    const int bn = (lane & 7) + ((lane >> 4) << 3);   // B: n within 16
    const int bk = ((lane >> 3) & 1) << 3;            // B: +8 cols

    for (int c = 0; c < 3; c++) {
        __syncthreads();
        for (int u = tid; u < H * 16; u += 256) {
            int n = u >> 4, t = u & 15;
            size_t g = (size_t)n * H + c * 64 + t * 4;
            *(u64t*)(Wb + n * WST + t * 8)         = *(const u64t*)(wh + g);
            *(u64t*)(Wb + L_WLO + n * WST + t * 8) = *(const u64t*)(wl + g);
        }
        __syncthreads();
#pragma unroll
        for (int s = 0; s < 4; s++) {
            const int k  = c * 64 + s * 16;   // A col (global K)
            const int kl = s * 16;            // W col (chunk-local)
            uint32_t afh[2][4], afl[2][4];
            ldsm4(afh[0], sbA  + (wm +      lr) * AST + (k + lk) * 2);
            ldsm4(afh[1], sbA  + (wm + 16 + lr) * AST + (k + lk) * 2);
            ldsm4(afl[0], sbAl + (wm +      lr) * AST + (k + lk) * 2);
            ldsm4(afl[1], sbAl + (wm + 16 + lr) * AST + (k + lk) * 2);
            uint32_t bfh[6][2], bfl[6][2];
#pragma unroll
            for (int p = 0; p < 3; p++) {
                uint32_t q[4];
                ldsm4(q, sbW + (wn + p * 16 + bn) * WST + (kl + bk) * 2);
                bfh[2*p][0] = q[0]; bfh[2*p][1] = q[1];
                bfh[2*p+1][0] = q[2]; bfh[2*p+1][1] = q[3];
                ldsm4(q, sbW + L_WLO + (wn + p * 16 + bn) * WST + (kl + bk) * 2);
                bfl[2*p][0] = q[0]; bfl[2*p][1] = q[1];
                bfl[2*p+1][0] = q[2]; bfl[2*p+1][1] = q[3];
            }
#pragma unroll
            for (int mi = 0; mi < 2; mi++)
#pragma unroll
                for (int ni = 0; ni < 6; ni++) {
                    mma_bf16(acc[mi][ni], afh[mi], bfh[ni]);
                    mma_bf16(acc[mi][ni], afh[mi], bfl[ni]);
                    mma_bf16(acc[mi][ni], afl[mi], bfh[ni]);
                }
        }
    }
    __syncthreads();

    // spill accum to Y (reuse W region), stride 200 floats
    float* Y = (float*)Wb;
    const int cr = lane >> 2, cc = (lane & 3) * 2;
#pragma unroll
    for (int mi = 0; mi < 2; mi++)
#pragma unroll
        for (int ni = 0; ni < 6; ni++) {
            int r = wm + 16 * mi + cr, cl = wn + 8 * ni + cc;
            *(float2*)(Y + r * 200 + cl)       = make_float2(acc[mi][ni][0], acc[mi][ni][1]);
            *(float2*)(Y + (r + 8) * 200 + cl) = make_float2(acc[mi][ni][2], acc[mi][ni][3]);
        }
    __syncthreads();

    // LayerNorm + ReLU + residual: 4 threads per row
    const int r = tid >> 2, q = tid & 3;
    const float* pb  = prm;
    const float* pg  = prm + H;
    const float* pbt = prm + 2 * H;
    float s = 0.f, s2 = 0.f;
#pragma unroll
    for (int i = 0; i < 48; i++) {
        int cx = q * 48 + i;
        float y = Y[r * 200 + cx] + pb[cx];
        s += y; s2 += y * y;
    }
    s  += __shfl_xor_sync(0xffffffffu, s, 1);  s  += __shfl_xor_sync(0xffffffffu, s, 2);
    s2 += __shfl_xor_sync(0xffffffffu, s2, 1); s2 += __shfl_xor_sync(0xffffffffu, s2, 2);
    const float inv = 1.f / (float)H;
    float mu = s * inv;
    float rstd = rsqrtf(fmaxf(s2 * inv - mu * mu, 0.f) + EPSLN);
    if (row0 + r < nrows) {
#pragma unroll
        for (int i = 0; i < 48; i += 2) {
            int cx = q * 48 + i;
            float y0 = Y[r * 200 + cx]     + pb[cx];
            float y1 = Y[r * 200 + cx + 1] + pb[cx + 1];
            float v0 = fmaxf((y0 - mu) * rstd * pg[cx]     + pbt[cx],     0.f);
            float v1 = fmaxf((y1 - mu) * rstd * pg[cx + 1] + pbt[cx + 1], 0.f);
            __nv_bfloat162 oh = *(const __nv_bfloat162*)(Ahi + r * AST + cx * 2);
            __nv_bfloat162 ol = *(const __nv_bfloat162*)(Alo + r * AST + cx * 2);
            float n0 = __bfloat162float(oh.x) + __bfloat162float(ol.x) + v0;
            float n1 = __bfloat162float(oh.y) + __bfloat162float(ol.y) + v1;
            __nv_bfloat16 a0, b0, a1, b1;
            fsplit(n0, a0, b0); fsplit(n1, a1, b1);
            size_t g = (size_t)(row0 + r) * H + cx;
            *(__nv_bfloat162*)(g_hhi + g) = __nv_bfloat162(a0, a1);
            *(__nv_bfloat162*)(g_hlo + g) = __nv_bfloat162(b0, b1);
        }
    }
}

// =====================================================================
// Head kernel: out = relu([h1|h2|df] @ W1^T + b1) . W2 + b2
// Same MMA structure; K=576 in 9 chunks of 64; A chunk gathered per-chunk.
// smem: Ahi[64x72*2B]=9216 | Alo 9216 | W 55296 (reused as Y) | prm 384 floats
// =====================================================================
#define HD_ALO 9216
#define HD_W   18432
#define HD_PRM 73728
#define HD_SMEM (73728 + 1536)

__global__ __launch_bounds__(256, 2)
void head_mm_kernel(const float* __restrict__ b1, const float* __restrict__ W2,
                    const float* __restrict__ b2, float* __restrict__ out, int Bm) {
    extern __shared__ __align__(128) char sm[];
    char* Ahi = sm;
    char* Alo = sm + HD_ALO;
    char* Wb  = sm + HD_W;
    float* prm = (float*)(sm + HD_PRM);

    const int tid = threadIdx.x;
    const int wid = tid >> 5, lane = tid & 31;
    const int row0 = blockIdx.x * 64;

    for (int e = tid; e < 2 * H; e += 256)
        prm[e] = (e < H) ? b1[e] : W2[e - H];

    const int wm = (wid & 1) * 32;
    const int wn = (wid >> 1) * 48;
    float acc[2][6][4];
#pragma unroll
    for (int mi = 0; mi < 2; mi++)
#pragma unroll
        for (int ni = 0; ni < 6; ni++)
#pragma unroll
            for (int j = 0; j < 4; j++) acc[mi][ni][j] = 0.f;

    const uint32_t sbA  = smem_u32(Ahi);
    const uint32_t sbAl = smem_u32(Alo);
    const uint32_t sbW  = smem_u32(Wb);
    const int lr = lane & 15;
    const int lk = (lane >> 4) << 3;
    const int bn = (lane & 7) + ((lane >> 4) << 3);
    const int bk = ((lane >> 3) & 1) << 3;

    for (int c = 0; c < 9; c++) {
        __syncthreads();
        // A chunk [64 x 64]
        for (int u = tid; u < 64 * 16; u += 256) {
            int r = u >> 4, t = u & 15;
            u64t vh = 0, vl = 0;
            int m = row0 + r;
            if (m < Bm) {
                if (c < 3) {
                    size_t g = (size_t)m * H + c * 64 + t * 4;
                    vh = *(const u64t*)(g_hhi + g); vl = *(const u64t*)(g_hlo + g);
                } else if (c < 6) {
                    size_t g = (size_t)(Bm + m) * H + (c - 3) * 64 + t * 4;
                    vh = *(const u64t*)(g_hhi + g); vl = *(const u64t*)(g_hlo + g);
                } else {
                    size_t g = (size_t)m * H + (c - 6) * 64 + t * 4;
                    vh = *(const u64t*)(g_dfhi + g); vl = *(const u64t*)(g_dflo + g);
                }
            }
            *(u64t*)(Ahi + r * WST + t * 8) = vh;
            *(u64t*)(Alo + r * WST + t * 8) = vl;
        }
        // W1 chunk [192 x 64]
        for (int u = tid; u < H * 16; u += 256) {
            int n = u >> 4, t = u & 15;
            size_t g = (size_t)n * H3 + c * 64 + t * 4;
            *(u64t*)(Wb + n * WST + t * 8)         = *(const u64t*)(g_W1hi + g);
            *(u64t*)(Wb + L_WLO + n * WST + t * 8) = *(const u64t*)(g_W1lo + g);
        }
        __syncthreads();
#pragma unroll
        for (int s = 0; s < 4; s++) {
            const int kl = s * 16;
            uint32_t afh[2][4], afl[2][4];
            ldsm4(afh[0], sbA  + (wm +      lr) * WST + (kl + lk) * 2);
            ldsm4(afh[1], sbA  + (wm + 16 + lr) * WST + (kl + lk) * 2);
            ldsm4(afl[0], sbAl + (wm +      lr) * WST + (kl + lk) * 2);
            ldsm4(afl[1], sbAl + (wm + 16 + lr) * WST + (kl + lk) * 2);
            uint32_t bfh[6][2], bfl[6][2];
#pragma unroll
            for (int p = 0; p < 3; p++) {
                uint32_t q[4];
                ldsm4(q, sbW + (wn + p * 16 + bn) * WST + (kl + bk) * 2);
                bfh[2*p][0] = q[0]; bfh[2*p][1] = q[1];
                bfh[2*p+1][0] = q[2]; bfh[2*p+1][1] = q[3];
                ldsm4(q, sbW + L_WLO + (wn + p * 16 + bn) * WST + (kl + bk) * 2);
                bfl[2*p][0] = q[0]; bfl[2*p][1] = q[1];
                bfl[2*p+1][0] = q[2]; bfl[2*p+1][1] = q[3];
            }
#pragma unroll
            for (int mi = 0; mi < 2; mi++)
#pragma unroll
                for (int ni = 0; ni < 6; ni++) {
                    mma_bf16(acc[mi][ni], afh[mi], bfh[ni]);
                    mma_bf16(acc[mi][ni], afh[mi], bfl[ni]);
                    mma_bf16(acc[mi][ni], afl[mi], bfh[ni]);
                }
        }
    }
    __syncthreads();

    float* Y = (float*)Wb;
    const int cr = lane >> 2, cc = (lane & 3) * 2;
#pragma unroll
    for (int mi = 0; mi < 2; mi++)
#pragma unroll
        for (int ni = 0; ni < 6; ni++) {
            int r = wm + 16 * mi + cr, cl = wn + 8 * ni + cc;
            *(float2*)(Y + r * 200 + cl)       = make_float2(acc[mi][ni][0], acc[mi][ni][1]);
            *(float2*)(Y + (r + 8) * 200 + cl) = make_float2(acc[mi][ni][2], acc[mi][ni][3]);
        }
    __syncthreads();

    const int r = tid >> 2, q = tid & 3;
    const float* pb1 = prm;
    const float* pw2 = prm + H;
    float s = 0.f;
#pragma unroll
    for (int i = 0; i < 48; i++) {
        int cx = q * 48 + i;
        float x = fmaxf(Y[r * 200 + cx] + pb1[cx], 0.f);
        s = fmaf(x, pw2[cx], s);
    }
    s += __shfl_xor_sync(0xffffffffu, s, 1);
    s += __shfl_xor_sync(0xffffffffu, s, 2);
    if (q == 0 && row0 + r < Bm) out[row0 + r] = s + b2[0];
}

// ===== launch =====
extern "C" void kernel_launch(void* const* d_in, const int* in_sizes, int n_in,
                              void* d_out, int out_size)
{
    const int*   z        = (const int*)  d_in[1];
    const float* pos      = (const float*)d_in[2];
    const int*   batch    = (const int*)  d_in[3];
    const float* emb      = (const float*)d_in[5];
    const float* layer_W  = (const float*)d_in[6];
    const float* layer_b  = (const float*)d_in[7];
    const float* layer_g  = (const float*)d_in[8];
    const float* layer_bt = (const float*)d_in[9];
    const float* dist_W   = (const float*)d_in[10];
    const float* dist_b   = (const float*)d_in[11];
    const float* head_W1  = (const float*)d_in[12];
    const float* head_b1  = (const float*)d_in[13];
    const float* head_W2  = (const float*)d_in[14];
    const float* head_b2  = (const float*)d_in[15];
    float* out = (float*)d_out;

    const int B = out_size;
    const int N = in_sizes[1];
    const int L = in_sizes[6] / (H * H);
    const int nrows = 2 * B;

    cudaFuncSetAttribute(layer_mm_kernel, cudaFuncAttributeMaxDynamicSharedMemorySize, L_SMEM);
    cudaFuncSetAttribute(head_mm_kernel,  cudaFuncAttributeMaxDynamicSharedMemorySize, HD_SMEM);

    findfirst_kernel<<<(N + 255) / 256, 256>>>(batch, N, B);
    gather_kernel<<<(2 * B * H + 255) / 256, 256>>>(z, emb, B);
    dist_kernel<<<(B + 255) / 256, 256>>>(pos, B);
    distfeat_kernel<<<(B * H + 255) / 256, 256>>>(dist_W, dist_b, B);
    convw_kernel<<<(L * H * H + H * H3 + 255) / 256, 256>>>(layer_W, head_W1, L);

    for (int l = 0; l < L; l++) {
        layer_mm_kernel<<<(nrows + 63) / 64, 256, L_SMEM>>>(
            l, layer_b + l * H, layer_g + l * H, layer_bt + l * H, nrows);
    }
    head_mm_kernel<<<(B + 63) / 64, 256, HD_SMEM>>>(head_b1, head_W2, head_b2, out, B);
}

// round 4
// speedup vs baseline: 3.3779x; 3.0736x over previous
#include <cuda_runtime.h>
#include <cuda_fp16.h>
#include <math.h>
#include <stdint.h>

#define H 192
#define H3 576
#define MAXB 200000
#define EPSLN 1e-5f
#define AST 400   // A smem row stride bytes (layer)
#define WST 144   // W / head-A smem row stride bytes

// ===== device scratch =====
__device__ int   g_first[MAXB + 1];
__device__ float g_dist[MAXB];
__device__ float g_h[2 * (size_t)MAXB * H];
__device__ __half g_Wh[5 * H * H];
__device__ __half g_W1h[H * H3];

// ===== helpers =====
__device__ __forceinline__ uint32_t smem_u32(const void* p) {
    uint32_t a;
    asm("{ .reg .u64 t; cvta.to.shared.u64 t, %1; cvt.u32.u64 %0, t; }" : "=r"(a) : "l"(p));
    return a;
}
__device__ __forceinline__ void ldsm4(uint32_t* r, uint32_t addr) {
    asm volatile("ldmatrix.sync.aligned.m8n8.x4.shared.b16 {%0,%1,%2,%3}, [%4];"
        : "=r"(r[0]), "=r"(r[1]), "=r"(r[2]), "=r"(r[3]) : "r"(addr));
}
__device__ __forceinline__ void mma_f16(float* c, const uint32_t* a, const uint32_t* b) {
    asm volatile("mma.sync.aligned.m16n8k16.row.col.f32.f16.f16.f32 "
        "{%0,%1,%2,%3}, {%4,%5,%6,%7}, {%8,%9}, {%0,%1,%2,%3};"
        : "+f"(c[0]), "+f"(c[1]), "+f"(c[2]), "+f"(c[3])
        : "r"(a[0]), "r"(a[1]), "r"(a[2]), "r"(a[3]), "r"(b[0]), "r"(b[1]));
}
__device__ __forceinline__ void cp16(uint32_t d, const void* s) {
    asm volatile("cp.async.cg.shared.global [%0], [%1], 16;" :: "r"(d), "l"(s));
}
#define CP_COMMIT() asm volatile("cp.async.commit_group;" ::: "memory")
#define CP_WAIT0()  asm volatile("cp.async.wait_group 0;" ::: "memory")

__device__ __forceinline__ void hsplit(float x, __half& hi, __half& lo) {
    hi = __float2half_rn(x);
    lo = __float2half_rn(x - __half2float(hi));
}

// ===== prep =====
__global__ __launch_bounds__(256)
void findfirst_kernel(const int* __restrict__ batch, int N, int B) {
    int i = blockIdx.x * blockDim.x + threadIdx.x;
    if (i == 0) g_first[B] = N;
    if (i >= N) return;
    if (i == 0 || batch[i] != batch[i - 1]) g_first[batch[i]] = i;
}

__global__ __launch_bounds__(256)
void dist_kernel(const float* __restrict__ pos, int B) {
    int m = blockIdx.x * blockDim.x + threadIdx.x;
    if (m >= B) return;
    int f = g_first[m], nf = g_first[m + 1];
    float d = 0.f;
    if (nf - f > 1) {
        int s = f + 1;
        float dx = pos[3*f+0]-pos[3*s+0], dy = pos[3*f+1]-pos[3*s+1], dz = pos[3*f+2]-pos[3*s+2];
        d = sqrtf(dx*dx + dy*dy + dz*dz + 1e-12f);
    }
    g_dist[m] = d;
}

__global__ __launch_bounds__(256)
void convw_kernel(const float* __restrict__ lW, const float* __restrict__ hW1, int L) {
    int idx = blockIdx.x * blockDim.x + threadIdx.x;
    int nlw = L * H * H;
    if (idx >= nlw + H * H3) return;
    if (idx < nlw) g_Wh[idx] = __float2half_rn(lW[idx]);
    else           g_W1h[idx - nlw] = __float2half_rn(hW1[idx - nlw]);
}

// =====================================================================
// Layer: h <- h + relu(LN(h @ W^T + b)*g + beta)
// Block 256 thr, tile M=64 x N=192; warps 2(M)x4(N), warp tile 32x48.
// A split fp16 hi+lo in smem (from fp32 h), W fp16 single, 2 MMAs/tile.
// smem: Ahi 25600 | Alo 25600 | W0 27648 | W1 27648 | prm 2304 | ps 1024 | pq 1024
// =====================================================================
#define L_ALO 25600
#define L_W   51200
#define L_PRM 106496
#define L_PS  108800
#define L_PQ  109824
#define L_SMEM 110848

__global__ __launch_bounds__(256, 2)
void layer_mm_kernel(int l, int first, const int* __restrict__ z,
                     const float* __restrict__ emb,
                     const float* __restrict__ bias, const float* __restrict__ gamma,
                     const float* __restrict__ beta, int nrows, int B)
{
    extern __shared__ __align__(128) char sm[];
    const uint32_t sb = smem_u32(sm);
    __half* Ahi = (__half*)sm;
    __half* Alo = (__half*)(sm + L_ALO);
    float* prm = (float*)(sm + L_PRM);
    float* ps  = (float*)(sm + L_PS);
    float* pq  = (float*)(sm + L_PQ);

    const int tid = threadIdx.x, wid = tid >> 5, lane = tid & 31;
    const int row0 = blockIdx.x * 64;
    const __half* wsrc = g_Wh + (size_t)l * H * H;

    // prefetch W chunk 0
    for (int u = tid; u < 1536; u += 256) {
        int n = u >> 3, seg = u & 7;
        cp16(sb + L_W + n * WST + seg * 16, wsrc + (size_t)n * H + seg * 8);
    }
    CP_COMMIT();

    for (int e = tid; e < 576; e += 256)
        prm[e] = (e < 192) ? bias[e] : (e < 384) ? gamma[e - 192] : beta[e - 384];

    // stage A (full K=192), fp32 -> fp16 hi/lo
    for (int u = tid; u < 64 * 48; u += 256) {
        int r = u / 48, t = u - r * 48;
        float4 v = make_float4(0.f, 0.f, 0.f, 0.f);
        int row = row0 + r;
        if (row < nrows) {
            if (first) {
                int m = (row < B) ? row : row - B;
                int f = g_first[m];
                int atom = (row >= B && (g_first[m + 1] - f) > 1) ? f + 1 : f;
                v = *(const float4*)(emb + (size_t)z[atom] * H + t * 4);
            } else {
                v = *(const float4*)(g_h + (size_t)row * H + t * 4);
            }
        }
        __half h0,h1,h2,h3,l0,l1,l2,l3;
        hsplit(v.x,h0,l0); hsplit(v.y,h1,l1); hsplit(v.z,h2,l2); hsplit(v.w,h3,l3);
        __half2* dh = (__half2*)(Ahi + r * 200 + t * 4);
        __half2* dl = (__half2*)(Alo + r * 200 + t * 4);
        dh[0] = __halves2half2(h0,h1); dh[1] = __halves2half2(h2,h3);
        dl[0] = __halves2half2(l0,l1); dl[1] = __halves2half2(l2,l3);
    }

    const int wm = (wid & 1) * 32, wn = (wid >> 1) * 48;
    float acc[2][6][4];
#pragma unroll
    for (int mi = 0; mi < 2; mi++)
#pragma unroll
        for (int ni = 0; ni < 6; ni++)
#pragma unroll
            for (int j = 0; j < 4; j++) acc[mi][ni][j] = 0.f;

    const int lr = lane & 15, lk = (lane >> 4) << 3;
    const int bn = (lane & 7) + ((lane >> 4) << 3), bk = ((lane >> 3) & 1) << 3;

    CP_WAIT0();
    __syncthreads();

    for (int c = 0; c < 3; c++) {
        if (c < 2) {
            uint32_t nb = sb + L_W + ((c + 1) & 1) * 27648u;
            for (int u = tid; u < 1536; u += 256) {
                int n = u >> 3, seg = u & 7;
                cp16(nb + n * WST + seg * 16, wsrc + (size_t)n * H + (c + 1) * 64 + seg * 8);
            }
            CP_COMMIT();
        }
        uint32_t wb = sb + L_W + (c & 1) * 27648u;
#pragma unroll
        for (int s = 0; s < 4; s++) {
            const int k = c * 64 + s * 16, kl = s * 16;
            uint32_t ah[2][4], al[2][4];
            ldsm4(ah[0], sb + (wm +      lr) * AST + (k + lk) * 2);
            ldsm4(ah[1], sb + (wm + 16 + lr) * AST + (k + lk) * 2);
            ldsm4(al[0], sb + L_ALO + (wm +      lr) * AST + (k + lk) * 2);
            ldsm4(al[1], sb + L_ALO + (wm + 16 + lr) * AST + (k + lk) * 2);
            uint32_t bf[6][2];
#pragma unroll
            for (int p = 0; p < 3; p++) {
                uint32_t q[4];
                ldsm4(q, wb + (wn + p * 16 + bn) * WST + (kl + bk) * 2);
                bf[2*p][0] = q[0]; bf[2*p][1] = q[1];
                bf[2*p+1][0] = q[2]; bf[2*p+1][1] = q[3];
            }
#pragma unroll
            for (int mi = 0; mi < 2; mi++)
#pragma unroll
                for (int ni = 0; ni < 6; ni++) {
                    mma_f16(acc[mi][ni], ah[mi], bf[ni]);
                    mma_f16(acc[mi][ni], al[mi], bf[ni]);
                }
        }
        if (c < 2) { CP_WAIT0(); __syncthreads(); }
    }

    // ===== epilogue: bias + LN stats (register/shuffle/smem-partials) =====
    const int c4 = lane & 3, lr4 = lane >> 2, wnIdx = wid >> 1;
    float sv[2][2] = {{0,0},{0,0}}, qv[2][2] = {{0,0},{0,0}};
#pragma unroll
    for (int mi = 0; mi < 2; mi++)
#pragma unroll
        for (int ni = 0; ni < 6; ni++) {
            int col = wn + 8 * ni + 2 * c4;
            float b0 = prm[col], b1 = prm[col + 1];
            acc[mi][ni][0] += b0; acc[mi][ni][1] += b1;
            acc[mi][ni][2] += b0; acc[mi][ni][3] += b1;
            sv[mi][0] += acc[mi][ni][0] + acc[mi][ni][1];
            qv[mi][0] += acc[mi][ni][0]*acc[mi][ni][0] + acc[mi][ni][1]*acc[mi][ni][1];
            sv[mi][1] += acc[mi][ni][2] + acc[mi][ni][3];
            qv[mi][1] += acc[mi][ni][2]*acc[mi][ni][2] + acc[mi][ni][3]*acc[mi][ni][3];
        }
#pragma unroll
    for (int o = 1; o <= 2; o <<= 1) {
#pragma unroll
        for (int mi = 0; mi < 2; mi++)
#pragma unroll
            for (int hf = 0; hf < 2; hf++) {
                sv[mi][hf] += __shfl_xor_sync(0xffffffffu, sv[mi][hf], o);
                qv[mi][hf] += __shfl_xor_sync(0xffffffffu, qv[mi][hf], o);
            }
    }
    if (c4 == 0) {
#pragma unroll
        for (int mi = 0; mi < 2; mi++)
#pragma unroll
            for (int hf = 0; hf < 2; hf++) {
                int row = wm + 16 * mi + 8 * hf + lr4;
                ps[row * 4 + wnIdx] = sv[mi][hf];
                pq[row * 4 + wnIdx] = qv[mi][hf];
            }
    }
    __syncthreads();

    float mu[2][2], rs[2][2];
#pragma unroll
    for (int mi = 0; mi < 2; mi++)
#pragma unroll
        for (int hf = 0; hf < 2; hf++) {
            int row = wm + 16 * mi + 8 * hf + lr4;
            float s = ps[row*4] + ps[row*4+1] + ps[row*4+2] + ps[row*4+3];
            float q2 = pq[row*4] + pq[row*4+1] + pq[row*4+2] + pq[row*4+3];
            float m_ = s * (1.f / 192.f);
            float v_ = q2 * (1.f / 192.f) - m_ * m_;
            mu[mi][hf] = m_;
            rs[mi][hf] = rsqrtf(fmaxf(v_, 0.f) + EPSLN);
        }

    const float* pg = prm + 192;
    const float* pbt = prm + 384;
#pragma unroll
    for (int mi = 0; mi < 2; mi++) {
        int ra = wm + 16 * mi + lr4, rb = ra + 8;
        bool oka = (row0 + ra < nrows), okb = (row0 + rb < nrows);
#pragma unroll
        for (int ni = 0; ni < 6; ni++) {
            int col = wn + 8 * ni + 2 * c4;
            float g0 = pg[col], g1 = pg[col+1], t0 = pbt[col], t1 = pbt[col+1];
            if (oka) {
                float v0 = fmaxf((acc[mi][ni][0] - mu[mi][0]) * rs[mi][0] * g0 + t0, 0.f);
                float v1 = fmaxf((acc[mi][ni][1] - mu[mi][0]) * rs[mi][0] * g1 + t1, 0.f);
                __half2 oh = *(__half2*)(Ahi + ra * 200 + col);
                __half2 ol = *(__half2*)(Alo + ra * 200 + col);
                float2 o;
                o.x = __low2float(oh)  + __low2float(ol)  + v0;
                o.y = __high2float(oh) + __high2float(ol) + v1;
                *(float2*)(g_h + (size_t)(row0 + ra) * H + col) = o;
            }
            if (okb) {
                float v0 = fmaxf((acc[mi][ni][2] - mu[mi][1]) * rs[mi][1] * g0 + t0, 0.f);
                float v1 = fmaxf((acc[mi][ni][3] - mu[mi][1]) * rs[mi][1] * g1 + t1, 0.f);
                __half2 oh = *(__half2*)(Ahi + rb * 200 + col);
                __half2 ol = *(__half2*)(Alo + rb * 200 + col);
                float2 o;
                o.x = __low2float(oh)  + __low2float(ol)  + v0;
                o.y = __high2float(oh) + __high2float(ol) + v1;
                *(float2*)(g_h + (size_t)(row0 + rb) * H + col) = o;
            }
        }
    }
}

// =====================================================================
// Head: out = relu([h1|h2|distfeat] @ W1^T + b1) . W2 + b2
// K=576 in 9 chunks; dist_feat synthesized during staging.
// smem: A[2 bufs: hi 9216 + lo 9216] | W0 27648 | W1 27648 | prm 3072 | part 1024
// =====================================================================
#define HD_W    36864
#define HD_PRM  92160
#define HD_PART 95232
#define HD_SMEM 96256

__global__ __launch_bounds__(256, 2)
void head_mm_kernel(const float* __restrict__ b1, const float* __restrict__ W2,
                    const float* __restrict__ b2,
                    const float* __restrict__ dW, const float* __restrict__ dB,
                    float* __restrict__ out, int Bm)
{
    extern __shared__ __align__(128) char sm[];
    const uint32_t sb = smem_u32(sm);
    float* prm  = (float*)(sm + HD_PRM);   // b1 | W2 | dW | dB
    float* part = (float*)(sm + HD_PART);

    const int tid = threadIdx.x, wid = tid >> 5, lane = tid & 31;
    const int row0 = blockIdx.x * 64;

    // prefetch W1 chunk 0
    for (int u = tid; u < 1536; u += 256) {
        int n = u >> 3, seg = u & 7;
        cp16(sb + HD_W + n * WST + seg * 16, g_W1h + (size_t)n * H3 + seg * 8);
    }
    CP_COMMIT();

    for (int e = tid; e < 768; e += 256)
        prm[e] = (e < 192) ? b1[e] : (e < 384) ? W2[e-192] : (e < 576) ? dW[e-384] : dB[e-576];
    __syncthreads();   // prm (dW/dB) needed by A staging below

    // stage A chunk c into buffer b
    auto stageA = [&](int c, int b) {
        __half* Ahi = (__half*)(sm + b * 18432);
        __half* Alo = (__half*)(sm + b * 18432 + 9216);
        for (int u = tid; u < 64 * 16; u += 256) {
            int r = u >> 4, t = u & 15;
            int m = row0 + r;
            float4 v = make_float4(0.f, 0.f, 0.f, 0.f);
            if (m < Bm) {
                if (c < 3)      v = *(const float4*)(g_h + (size_t)m * H + c * 64 + t * 4);
                else if (c < 6) v = *(const float4*)(g_h + ((size_t)Bm + m) * H + (c - 3) * 64 + t * 4);
                else {
                    int k = (c - 6) * 64 + t * 4;
                    float d = g_dist[m];
                    v.x = d * prm[384 + k]     + prm[576 + k];
                    v.y = d * prm[384 + k + 1] + prm[576 + k + 1];
                    v.z = d * prm[384 + k + 2] + prm[576 + k + 2];
                    v.w = d * prm[384 + k + 3] + prm[576 + k + 3];
                }
            }
            __half h0,h1,h2,h3,l0,l1,l2,l3;
            hsplit(v.x,h0,l0); hsplit(v.y,h1,l1); hsplit(v.z,h2,l2); hsplit(v.w,h3,l3);
            __half2* dh = (__half2*)(Ahi + r * 72 + t * 4);
            __half2* dl = (__half2*)(Alo + r * 72 + t * 4);
            dh[0] = __halves2half2(h0,h1); dh[1] = __halves2half2(h2,h3);
            dl[0] = __halves2half2(l0,l1); dl[1] = __halves2half2(l2,l3);
        }
    };
    stageA(0, 0);

    const int wm = (wid & 1) * 32, wn = (wid >> 1) * 48;
    float acc[2][6][4];
#pragma unroll
    for (int mi = 0; mi < 2; mi++)
#pragma unroll
        for (int ni = 0; ni < 6; ni++)
#pragma unroll
            for (int j = 0; j < 4; j++) acc[mi][ni][j] = 0.f;

    const int lr = lane & 15, lk = (lane >> 4) << 3;
    const int bn = (lane & 7) + ((lane >> 4) << 3), bk = ((lane >> 3) & 1) << 3;

    CP_WAIT0();
    __syncthreads();

    for (int c = 0; c < 9; c++) {
        if (c < 8) {
            uint32_t nb = sb + HD_W + ((c + 1) & 1) * 27648u;
            for (int u = tid; u < 1536; u += 256) {
                int n = u >> 3, seg = u & 7;
                cp16(nb + n * WST + seg * 16, g_W1h + (size_t)n * H3 + (c + 1) * 64 + seg * 8);
            }
            CP_COMMIT();
            stageA(c + 1, (c + 1) & 1);
        }
        uint32_t ab = sb + (c & 1) * 18432u;
        uint32_t wb = sb + HD_W + (c & 1) * 27648u;
#pragma unroll
        for (int s = 0; s < 4; s++) {
            const int kl = s * 16;
            uint32_t ah[2][4], al[2][4];
            ldsm4(ah[0], ab + (wm +      lr) * WST + (kl + lk) * 2);
            ldsm4(ah[1], ab + (wm + 16 + lr) * WST + (kl + lk) * 2);
            ldsm4(al[0], ab + 9216 + (wm +      lr) * WST + (kl + lk) * 2);
            ldsm4(al[1], ab + 9216 + (wm + 16 + lr) * WST + (kl + lk) * 2);
            uint32_t bf[6][2];
#pragma unroll
            for (int p = 0; p < 3; p++) {
                uint32_t q[4];
                ldsm4(q, wb + (wn + p * 16 + bn) * WST + (kl + bk) * 2);
                bf[2*p][0] = q[0]; bf[2*p][1] = q[1];
                bf[2*p+1][0] = q[2]; bf[2*p+1][1] = q[3];
            }
#pragma unroll
            for (int mi = 0; mi < 2; mi++)
#pragma unroll
                for (int ni = 0; ni < 6; ni++) {
                    mma_f16(acc[mi][ni], ah[mi], bf[ni]);
                    mma_f16(acc[mi][ni], al[mi], bf[ni]);
                }
        }
        if (c < 8) { CP_WAIT0(); __syncthreads(); }
    }

    // epilogue: relu(y+b1) . W2
    const int c4 = lane & 3, lr4 = lane >> 2, wnIdx = wid >> 1;
    float pv[2][2] = {{0,0},{0,0}};
#pragma unroll
    for (int mi = 0; mi < 2; mi++)
#pragma unroll
        for (int ni = 0; ni < 6; ni++) {
            int col = wn + 8 * ni + 2 * c4;
            float b0 = prm[col], b1v = prm[col + 1];
            float w0 = prm[192 + col], w1 = prm[192 + col + 1];
            pv[mi][0] += fmaxf(acc[mi][ni][0] + b0, 0.f) * w0 + fmaxf(acc[mi][ni][1] + b1v, 0.f) * w1;
            pv[mi][1] += fmaxf(acc[mi][ni][2] + b0, 0.f) * w0 + fmaxf(acc[mi][ni][3] + b1v, 0.f) * w1;
        }
#pragma unroll
    for (int o = 1; o <= 2; o <<= 1)
#pragma unroll
        for (int mi = 0; mi < 2; mi++)
#pragma unroll
            for (int hf = 0; hf < 2; hf++)
                pv[mi][hf] += __shfl_xor_sync(0xffffffffu, pv[mi][hf], o);
    if (c4 == 0) {
#pragma unroll
        for (int mi = 0; mi < 2; mi++)
#pragma unroll
            for (int hf = 0; hf < 2; hf++) {
                int row = wm + 16 * mi + 8 * hf + lr4;
                part[row * 4 + wnIdx] = pv[mi][hf];
            }
    }
    __syncthreads();
    if (tid < 64 && row0 + tid < Bm) {
        out[row0 + tid] = part[tid*4] + part[tid*4+1] + part[tid*4+2] + part[tid*4+3] + b2[0];
    }
}

// ===== launch =====
extern "C" void kernel_launch(void* const* d_in, const int* in_sizes, int n_in,
                              void* d_out, int out_size)
{
    const int*   z        = (const int*)  d_in[1];
    const float* pos      = (const float*)d_in[2];
    const int*   batch    = (const int*)  d_in[3];
    const float* emb      = (const float*)d_in[5];
    const float* layer_W  = (const float*)d_in[6];
    const float* layer_b  = (const float*)d_in[7];
    const float* layer_g  = (const float*)d_in[8];
    const float* layer_bt = (const float*)d_in[9];
    const float* dist_W   = (const float*)d_in[10];
    const float* dist_b   = (const float*)d_in[11];
    const float* head_W1  = (const float*)d_in[12];
    const float* head_b1  = (const float*)d_in[13];
    const float* head_W2  = (const float*)d_in[14];
    const float* head_b2  = (const float*)d_in[15];
    float* out = (float*)d_out;

    const int B = out_size;
    const int N = in_sizes[1];
    const int L = in_sizes[6] / (H * H);
    const int nrows = 2 * B;

    cudaFuncSetAttribute(layer_mm_kernel, cudaFuncAttributeMaxDynamicSharedMemorySize, L_SMEM);
    cudaFuncSetAttribute(head_mm_kernel,  cudaFuncAttributeMaxDynamicSharedMemorySize, HD_SMEM);

    findfirst_kernel<<<(N + 255) / 256, 256>>>(batch, N, B);
    dist_kernel<<<(B + 255) / 256, 256>>>(pos, B);
    convw_kernel<<<(L * H * H + H * H3 + 255) / 256, 256>>>(layer_W, head_W1, L);

    for (int l = 0; l < L; l++) {
        layer_mm_kernel<<<(nrows + 63) / 64, 256, L_SMEM>>>(
            l, (l == 0) ? 1 : 0, z, emb,
            layer_b + l * H, layer_g + l * H, layer_bt + l * H, nrows, B);
    }
    head_mm_kernel<<<(B + 63) / 64, 256, HD_SMEM>>>(
        head_b1, head_W2, head_b2, dist_W, dist_b, out, B);
}